// round 1
// baseline (speedup 1.0000x reference)
#include <cuda_runtime.h>

#define BB 128
#define NN 512
#define CF 64
#define ALPHA_ 0.2f
#define WTS_STRIDE 33

// scratch (allocation-free rule: __device__ globals)
__device__ __align__(16) float g_h1[BB * NN * CF];
__device__ __align__(16) float g_diff[BB * NN * CF];
__device__ float g_s1[BB * NN];
__device__ float g_s2[BB * NN];

// ---------------------------------------------------------------------------
// Kernel 1: h0 = x@W0, h1 = x@W1 ; store h1, diff=h0-h1, s1=(h0+h1)@a1, s2=...@a2
// 256 threads, 64 rows per block, grid = 65536/64 = 1024
// ---------------------------------------------------------------------------
__global__ __launch_bounds__(256) void gat_gemm_kernel(
    const float* __restrict__ x, const float* __restrict__ W,
    const float* __restrict__ a)
{
    __shared__ float W0s[CF * CF];
    __shared__ float W1s[CF * CF];
    __shared__ float xs[16 * CF];
    __shared__ float redbuf[16][2][2];

    int t = threadIdx.x;
    for (int idx = t; idx < CF * CF; idx += 256) {
        W0s[idx] = W[idx];
        W1s[idx] = W[CF * CF + idx];
    }
    int f = t & 63;
    int g = t >> 6;           // 0..3, each group handles 4 rows
    float a1f = __ldg(&a[f]);
    float a2f = __ldg(&a[CF + f]);
    __syncthreads();

    int rowBase = blockIdx.x * 64;
    for (int it = 0; it < 4; it++) {
        int r0 = rowBase + it * 16;
        // load 16 rows of x (1024 floats = 256 float4)
        ((float4*)xs)[t] = ((const float4*)(x + (size_t)r0 * CF))[t];
        __syncthreads();

        float acc0[4] = {0.f, 0.f, 0.f, 0.f};
        float acc1[4] = {0.f, 0.f, 0.f, 0.f};
        #pragma unroll 4
        for (int c = 0; c < CF; c++) {
            float w0 = W0s[c * CF + f];
            float w1 = W1s[c * CF + f];
            #pragma unroll
            for (int rr = 0; rr < 4; rr++) {
                float xv = xs[(g * 4 + rr) * CF + c];
                acc0[rr] = fmaf(xv, w0, acc0[rr]);
                acc1[rr] = fmaf(xv, w1, acc1[rr]);
            }
        }

        int lane = t & 31;
        int half = (t >> 5) & 1;
        #pragma unroll
        for (int rr = 0; rr < 4; rr++) {
            int row = r0 + g * 4 + rr;
            float h1v = acc1[rr];
            float h0v = acc0[rr];
            g_h1[(size_t)row * CF + f] = h1v;
            g_diff[(size_t)row * CF + f] = h0v - h1v;
            float hs = h0v + h1v;
            float p1 = hs * a1f;
            float p2 = hs * a2f;
            #pragma unroll
            for (int o = 16; o; o >>= 1) {
                p1 += __shfl_xor_sync(0xffffffffu, p1, o);
                p2 += __shfl_xor_sync(0xffffffffu, p2, o);
            }
            if (lane == 0) {
                redbuf[g * 4 + rr][half][0] = p1;
                redbuf[g * 4 + rr][half][1] = p2;
            }
        }
        __syncthreads();
        if (t < 16) {
            int row = r0 + t;
            g_s1[row] = redbuf[t][0][0] + redbuf[t][1][0];
            g_s2[row] = redbuf[t][0][1] + redbuf[t][1][1];
        }
        __syncthreads();
    }
}

// ---------------------------------------------------------------------------
// Kernel 2: masked softmax attention + aggregation. 1 CTA per batch.
// smem: h1 tile [512][16]f4, wt transposed [512][33], s1/s2, sums, diag, bias
// 16 phases of 32 i's; phase A = warp-local softmax; phase B = 4i x 4f x jq tile
// ---------------------------------------------------------------------------
#define SMEM_FLOATS (32768 + NN * WTS_STRIDE + NN + NN + 32 + 32 + 64)
#define SMEM_BYTES (SMEM_FLOATS * 4)

__global__ __launch_bounds__(512) void gat_attn_kernel(
    const int* __restrict__ adj, const float* __restrict__ bias,
    float* __restrict__ out)
{
    extern __shared__ float sm[];
    float4* h1s4 = (float4*)sm;                  // 512*16 float4 (32768 floats)
    float*  wts  = sm + 32768;                    // 512*33
    float*  s2s  = wts + NN * WTS_STRIDE;         // 512
    float*  s1s  = s2s + NN;                      // 512
    float*  sums = s1s + NN;                      // 32
    float*  diagw = sums + 32;                    // 32
    float*  biass = diagw + 32;                   // 64

    int b = blockIdx.x;
    int t = threadIdx.x;

    // load h1 tile for this batch (32768 floats = 8192 float4)
    {
        const float4* src = (const float4*)(g_h1 + (size_t)b * NN * CF);
        #pragma unroll
        for (int k = 0; k < 16; k++) h1s4[t + k * 512] = src[t + k * 512];
    }
    s2s[t] = g_s2[b * NN + t];
    s1s[t] = g_s1[b * NN + t];
    if (t < 64) biass[t] = bias[t];
    __syncthreads();

    int warpId = t >> 5, lane = t & 31;
    int jq = t >> 7;                // 0..3 j-quarter
    int slot = t & 127;
    int fi = slot & 15;             // float4 feature index 0..15
    int i0 = (slot >> 4) << 2;      // local i base (0,4,...,28)

    for (int ph = 0; ph < 16; ph++) {
        int iBase = ph * 32;

        // ---- Phase A: each warp computes softmax weights for 2 i's ----
        #pragma unroll
        for (int r = 0; r < 2; r++) {
            int il = (warpId << 1) | r;
            int i = iBase + il;
            float s1i = s1s[i];
            const int* arow = adj + (size_t)i * NN;
            float v[16];
            float m = -1e30f;
            #pragma unroll
            for (int k = 0; k < 16; k++) {
                int j = lane + (k << 5);
                float tv = s1i + s2s[j];
                tv = tv > 0.f ? tv : ALPHA_ * tv;
                v[k] = (__ldg(arow + j) > 0) ? tv : -1e30f;
                m = fmaxf(m, v[k]);
            }
            #pragma unroll
            for (int o = 16; o; o >>= 1)
                m = fmaxf(m, __shfl_xor_sync(0xffffffffu, m, o));
            float s = 0.f;
            #pragma unroll
            for (int k = 0; k < 16; k++) {
                float w = __expf(v[k] - m);
                s += w;
                wts[(lane + (k << 5)) * WTS_STRIDE + il] = w;
            }
            #pragma unroll
            for (int o = 16; o; o >>= 1)
                s += __shfl_xor_sync(0xffffffffu, s, o);
            if (lane == 0) sums[il] = s;
        }
        __syncthreads();

        // ---- Phase B: acc[4i][4f] over this thread's j-quarter ----
        float4 acc[4];
        acc[0] = make_float4(0.f, 0.f, 0.f, 0.f);
        acc[1] = acc[0]; acc[2] = acc[0]; acc[3] = acc[0];
        const float4* hp = h1s4 + (jq * 128) * 16 + fi;
        const float*  wp = wts + (jq * 128) * WTS_STRIDE + i0;
        #pragma unroll 4
        for (int jj = 0; jj < 128; jj++) {
            float w0 = wp[0], w1 = wp[1], w2 = wp[2], w3 = wp[3];
            float4 h = *hp;
            acc[0].x = fmaf(w0, h.x, acc[0].x);
            acc[0].y = fmaf(w0, h.y, acc[0].y);
            acc[0].z = fmaf(w0, h.z, acc[0].z);
            acc[0].w = fmaf(w0, h.w, acc[0].w);
            acc[1].x = fmaf(w1, h.x, acc[1].x);
            acc[1].y = fmaf(w1, h.y, acc[1].y);
            acc[1].z = fmaf(w1, h.z, acc[1].z);
            acc[1].w = fmaf(w1, h.w, acc[1].w);
            acc[2].x = fmaf(w2, h.x, acc[2].x);
            acc[2].y = fmaf(w2, h.y, acc[2].y);
            acc[2].z = fmaf(w2, h.z, acc[2].z);
            acc[2].w = fmaf(w2, h.w, acc[2].w);
            acc[3].x = fmaf(w3, h.x, acc[3].x);
            acc[3].y = fmaf(w3, h.y, acc[3].y);
            acc[3].z = fmaf(w3, h.z, acc[3].z);
            acc[3].w = fmaf(w3, h.w, acc[3].w);
            hp += 16;
            wp += WTS_STRIDE;
        }
        __syncthreads();   // all reads of wts done

        // extract diagonal weights before overwriting wts
        if (t < 32) diagw[t] = wts[(iBase + t) * WTS_STRIDE + t];
        __syncthreads();

        // partial reduction buffer aliased over wts region
        float4* red4 = (float4*)wts;
        #pragma unroll
        for (int aIdx = 0; aIdx < 4; aIdx++)
            red4[(jq * 32 + i0 + aIdx) * 16 + fi] = acc[aIdx];
        __syncthreads();

        // combine + diag correction + bias, write out
        {
            int il = t >> 4;
            int fc = t & 15;
            float4 tot = red4[il * 16 + fc];
            #pragma unroll
            for (int q = 1; q < 4; q++) {
                float4 p = red4[(q * 32 + il) * 16 + fc];
                tot.x += p.x; tot.y += p.y; tot.z += p.z; tot.w += p.w;
            }
            int i = iBase + il;
            float inv = 1.0f / sums[il];
            float wii = diagw[il];
            float4 df = __ldg((const float4*)g_diff + ((size_t)b * NN + i) * 16 + fc);
            float4 bs = ((const float4*)biass)[fc];
            float4 o;
            o.x = (tot.x + wii * df.x) * inv + bs.x;
            o.y = (tot.y + wii * df.y) * inv + bs.y;
            o.z = (tot.z + wii * df.z) * inv + bs.z;
            o.w = (tot.w + wii * df.w) * inv + bs.w;
            ((float4*)out)[((size_t)b * NN + i) * 16 + fc] = o;
        }
        __syncthreads();   // red region becomes wts again next phase
    }
}

// ---------------------------------------------------------------------------
extern "C" void kernel_launch(void* const* d_in, const int* in_sizes, int n_in,
                              void* d_out, int out_size) {
    const float* x    = (const float*)d_in[0];
    const int*   adj  = (const int*)d_in[1];
    const float* W    = (const float*)d_in[2];
    const float* a    = (const float*)d_in[3];
    const float* bias = (const float*)d_in[4];
    float* out = (float*)d_out;

    cudaFuncSetAttribute(gat_attn_kernel,
                         cudaFuncAttributeMaxDynamicSharedMemorySize, SMEM_BYTES);

    gat_gemm_kernel<<<(BB * NN) / 64, 256>>>(x, W, a);
    gat_attn_kernel<<<BB, 512, SMEM_BYTES>>>(adj, bias, out);
}